// round 5
// baseline (speedup 1.0000x reference)
#include <cuda_runtime.h>
#include <cstddef>

#define N_SRC   16384
#define N_TGT   65536
#define KNBR    8
#define CCH     16
#define CSKIP   2
#define SSC     32
#define HID     64
#define MVD     16
#define ROW_MV  (CCH*MVD)      // 256
#define TPB     128
#define TGT_PER_BLOCK 16
#define HA_STRIDE 68
#define SK_STRIDE 36

__device__ float g_Weff[(CCH + CSKIP) * CCH];   // 18x16 fused mv weight
__device__ float g_mvT[(size_t)N_SRC * ROW_MV]; // mv_src @ Weff[0:16]  (16 MB)
__device__ float g_scT[(size_t)N_SRC * HID];    // sc_src @ W1a         (4 MB)

// ---------------------------------------------------------------------------
__global__ void prep_weff(const float* __restrict__ W1_mv,
                          const float* __restrict__ W2_mv)
{
    int idx = threadIdx.x;
    if (idx < (CCH + CSKIP) * CCH) {
        int cp = idx >> 4;
        int c  = idx & 15;
        float acc = 0.f;
        #pragma unroll
        for (int h = 0; h < HID; h++)
            acc = fmaf(W1_mv[cp * HID + h], W2_mv[h * CCH + c], acc);
        g_Weff[idx] = acc;
    }
}

// g_mvT[s, c, i] = sum_cp mv_src[s, cp, i] * Weff[cp, c]   (block per source row)
__global__ void prep_mv(const float* __restrict__ mv_src)
{
    __shared__ float row[256];
    __shared__ float we[256];
    const int s = blockIdx.x, tid = threadIdx.x;
    row[tid] = mv_src[(size_t)s * 256 + tid];
    we[tid]  = g_Weff[tid];
    __syncthreads();
    const int c = tid >> 4, i = tid & 15;
    float acc = 0.f;
    #pragma unroll
    for (int cp = 0; cp < 16; cp++)
        acc = fmaf(row[cp * 16 + i], we[cp * 16 + c], acc);
    g_mvT[(size_t)s * 256 + tid] = acc;   // tid == c*16 + i
}

// g_scT[s, h] = sum_j sc_src[s, j] * W1_s[j, h]  (first 32 rows of W1_s)
__global__ void prep_sc(const float* __restrict__ sc_src,
                        const float* __restrict__ W1_s)
{
    __shared__ float x[4][32];
    __shared__ float w[SSC * HID];
    const int tid = threadIdx.x;
    const int s0 = blockIdx.x * 4;
    if (tid < 128) x[tid >> 5][tid & 31] = sc_src[(size_t)s0 * 32 + tid];
    for (int i = tid; i < SSC * HID; i += 256) w[i] = W1_s[i];
    __syncthreads();
    const int r = tid >> 6, h = tid & 63;
    float acc = 0.f;
    #pragma unroll
    for (int j = 0; j < 32; j++)
        acc = fmaf(x[r][j], w[j * HID + h], acc);
    g_scT[(size_t)(s0 + r) * HID + h] = acc;
}

__device__ __forceinline__ float gelu_tanh(float x)
{
    const float c0 = 0.7978845608028654f;
    float u = c0 * fmaf(0.044715f * x, x * x, x);
    float t = tanhf(u);
    return 0.5f * x * (1.0f + t);
}

// ---------------------------------------------------------------------------
// Warp-private pipeline: warp w owns targets {4w .. 4w+3}.
// Gather reads PRE-TRANSFORMED sources, so the accumulator IS the output.
// ---------------------------------------------------------------------------
__global__ __launch_bounds__(TPB, 6) void fused_kernel(
    const float* __restrict__ mv_skip, const float* __restrict__ sc_skip,
    const float* __restrict__ pos_src, const float* __restrict__ pos_tgt,
    const int*   __restrict__ isrc,
    const float* __restrict__ W1_s,    const float* __restrict__ b1_s,
    const float* __restrict__ W2_s,    const float* __restrict__ b2_s,
    float* __restrict__ out_mv,        float* __restrict__ out_sc)
{
    __shared__ __align__(16) float sHA[TGT_PER_BLOCK * HA_STRIDE];  // interp hidden (x64), then h in-place
    __shared__ __align__(16) float sSK[TGT_PER_BLOCK * SK_STRIDE];  // sc_skip stage

    const int tid  = threadIdx.x;
    const int lane = tid & 31;
    const int warp = tid >> 5;               // 0..3, owns rows 4w..4w+3
    const int tbase = blockIdx.x * TGT_PER_BLOCK;
    const int r0 = warp * 4;

    // ---------------- Phase 1: IDW gather of transformed sources ------------
    #pragma unroll
    for (int u = 0; u < 4; u++) {
        const int tl = r0 + u;
        const int t  = tbase + tl;

        float wk = 0.f;
        int   sk = 0;
        if (lane < KNBR) {
            sk = isrc[t * KNBR + lane];
            float dx = pos_src[sk * 3 + 0] - pos_tgt[t * 3 + 0];
            float dy = pos_src[sk * 3 + 1] - pos_tgt[t * 3 + 1];
            float dz = pos_src[sk * 3 + 2] - pos_tgt[t * 3 + 2];
            float d2 = fmaf(dx, dx, fmaf(dy, dy, dz * dz));
            d2 = fmaxf(d2, 1e-16f);
            wk = 1.0f / d2;
        }
        float den = wk;
        #pragma unroll
        for (int o = 16; o; o >>= 1) den += __shfl_xor_sync(0xffffffffu, den, o);
        const float invd = 1.0f / den;

        float4 a0 = make_float4(0.f, 0.f, 0.f, 0.f);
        float4 a1 = make_float4(0.f, 0.f, 0.f, 0.f);
        float  h0 = 0.f, h1 = 0.f;
        #pragma unroll
        for (int k = 0; k < KNBR; k++) {
            const float w = __shfl_sync(0xffffffffu, wk, k);
            const int   s = __shfl_sync(0xffffffffu, sk, k);
            const float4* row = (const float4*)(g_mvT + (size_t)s * ROW_MV);
            float4 v0 = __ldg(row + lane);
            float4 v1 = __ldg(row + lane + 32);
            a0.x = fmaf(w, v0.x, a0.x); a0.y = fmaf(w, v0.y, a0.y);
            a0.z = fmaf(w, v0.z, a0.z); a0.w = fmaf(w, v0.w, a0.w);
            a1.x = fmaf(w, v1.x, a1.x); a1.y = fmaf(w, v1.y, a1.y);
            a1.z = fmaf(w, v1.z, a1.z); a1.w = fmaf(w, v1.w, a1.w);
            h0 = fmaf(w, __ldg(g_scT + (size_t)s * HID + lane), h0);
            h1 = fmaf(w, __ldg(g_scT + (size_t)s * HID + 32 + lane), h1);
        }
        a0.x *= invd; a0.y *= invd; a0.z *= invd; a0.w *= invd;
        a1.x *= invd; a1.y *= invd; a1.z *= invd; a1.w *= invd;

        // skip correction: out[c][i] += skip0[i]*We[16][c] + skip1[i]*We[17][c]
        const int c0 = lane >> 2;
        const int ib = 4 * (lane & 3);
        float4 sk0 = __ldg((const float4*)(mv_skip + (size_t)t * 32 + ib));
        float4 sk1 = __ldg((const float4*)(mv_skip + (size_t)t * 32 + 16 + ib));
        const float wa16 = __ldg(g_Weff + 256 + c0);
        const float wa17 = __ldg(g_Weff + 272 + c0);
        const float wb16 = __ldg(g_Weff + 256 + 8 + c0);
        const float wb17 = __ldg(g_Weff + 272 + 8 + c0);
        a0.x = fmaf(sk0.x, wa16, fmaf(sk1.x, wa17, a0.x));
        a0.y = fmaf(sk0.y, wa16, fmaf(sk1.y, wa17, a0.y));
        a0.z = fmaf(sk0.z, wa16, fmaf(sk1.z, wa17, a0.z));
        a0.w = fmaf(sk0.w, wa16, fmaf(sk1.w, wa17, a0.w));
        a1.x = fmaf(sk0.x, wb16, fmaf(sk1.x, wb17, a1.x));
        a1.y = fmaf(sk0.y, wb16, fmaf(sk1.y, wb17, a1.y));
        a1.z = fmaf(sk0.z, wb16, fmaf(sk1.z, wb17, a1.z));
        a1.w = fmaf(sk0.w, wb16, fmaf(sk1.w, wb17, a1.w));

        float4* dst = (float4*)(out_mv + (size_t)t * ROW_MV);
        dst[lane]      = a0;
        dst[lane + 32] = a1;

        sHA[tl * HA_STRIDE + lane]      = h0 * invd;
        sHA[tl * HA_STRIDE + 32 + lane] = h1 * invd;
        sSK[tl * SK_STRIDE + lane]      = sc_skip[(size_t)t * SSC + lane];
    }
    __syncwarp();

    // ---------------- Phase 3a: hidden = gelu(interp_part + skip@W1b + b1) --
    // warp = 4 targets; lane = h-pair (h = 2*lane, 2*lane+1)
    {
        float2 bb = __ldg((const float2*)(b1_s + 2 * lane));
        float2 i0 = *(const float2*)(sHA + (r0 + 0) * HA_STRIDE + 2 * lane);
        float2 i1 = *(const float2*)(sHA + (r0 + 1) * HA_STRIDE + 2 * lane);
        float2 i2 = *(const float2*)(sHA + (r0 + 2) * HA_STRIDE + 2 * lane);
        float2 i3 = *(const float2*)(sHA + (r0 + 3) * HA_STRIDE + 2 * lane);
        float a0x = bb.x + i0.x, a0y = bb.y + i0.y;
        float a1x = bb.x + i1.x, a1y = bb.y + i1.y;
        float a2x = bb.x + i2.x, a2y = bb.y + i2.y;
        float a3x = bb.x + i3.x, a3y = bb.y + i3.y;
        const float* x0 = sSK + (r0 + 0) * SK_STRIDE;
        const float* x1 = sSK + (r0 + 1) * SK_STRIDE;
        const float* x2 = sSK + (r0 + 2) * SK_STRIDE;
        const float* x3 = sSK + (r0 + 3) * SK_STRIDE;
        #pragma unroll
        for (int jc = 0; jc < 8; jc++) {
            float4 v0 = *(const float4*)(x0 + 4 * jc);   // broadcast
            float4 v1 = *(const float4*)(x1 + 4 * jc);
            float4 v2 = *(const float4*)(x2 + 4 * jc);
            float4 v3 = *(const float4*)(x3 + 4 * jc);
            #pragma unroll
            for (int r = 0; r < 4; r++) {
                const int j = 4 * jc + r;               // skip row index
                float2 wv = __ldg((const float2*)(W1_s + (SSC + j) * HID + 2 * lane));
                const float e0 = (r == 0) ? v0.x : (r == 1) ? v0.y : (r == 2) ? v0.z : v0.w;
                const float e1 = (r == 0) ? v1.x : (r == 1) ? v1.y : (r == 2) ? v1.z : v1.w;
                const float e2 = (r == 0) ? v2.x : (r == 1) ? v2.y : (r == 2) ? v2.z : v2.w;
                const float e3 = (r == 0) ? v3.x : (r == 1) ? v3.y : (r == 2) ? v3.z : v3.w;
                a0x = fmaf(e0, wv.x, a0x); a0y = fmaf(e0, wv.y, a0y);
                a1x = fmaf(e1, wv.x, a1x); a1y = fmaf(e1, wv.y, a1y);
                a2x = fmaf(e2, wv.x, a2x); a2y = fmaf(e2, wv.y, a2y);
                a3x = fmaf(e3, wv.x, a3x); a3y = fmaf(e3, wv.y, a3y);
            }
        }
        // in-place write (each thread writes exactly the addresses it read)
        *(float2*)(sHA + (r0 + 0) * HA_STRIDE + 2 * lane) = make_float2(gelu_tanh(a0x), gelu_tanh(a0y));
        *(float2*)(sHA + (r0 + 1) * HA_STRIDE + 2 * lane) = make_float2(gelu_tanh(a1x), gelu_tanh(a1y));
        *(float2*)(sHA + (r0 + 2) * HA_STRIDE + 2 * lane) = make_float2(gelu_tanh(a2x), gelu_tanh(a2y));
        *(float2*)(sHA + (r0 + 3) * HA_STRIDE + 2 * lane) = make_float2(gelu_tanh(a3x), gelu_tanh(a3y));
    }
    __syncwarp();

    // ---------------- Phase 3b: scalar output (lane = channel) --------------
    {
        const float bb = __ldg(b2_s + lane);
        float a0 = bb, a1 = bb, a2 = bb, a3 = bb;
        const float* h0 = sHA + (r0 + 0) * HA_STRIDE;
        const float* h1 = sHA + (r0 + 1) * HA_STRIDE;
        const float* h2 = sHA + (r0 + 2) * HA_STRIDE;
        const float* h3 = sHA + (r0 + 3) * HA_STRIDE;
        #pragma unroll
        for (int hc = 0; hc < 16; hc++) {
            float4 v0 = *(const float4*)(h0 + 4 * hc);   // broadcast
            float4 v1 = *(const float4*)(h1 + 4 * hc);
            float4 v2 = *(const float4*)(h2 + 4 * hc);
            float4 v3 = *(const float4*)(h3 + 4 * hc);
            #pragma unroll
            for (int r = 0; r < 4; r++) {
                const int j = 4 * hc + r;
                float wv = __ldg(W2_s + j * SSC + lane);
                const float e0 = (r == 0) ? v0.x : (r == 1) ? v0.y : (r == 2) ? v0.z : v0.w;
                const float e1 = (r == 0) ? v1.x : (r == 1) ? v1.y : (r == 2) ? v1.z : v1.w;
                const float e2 = (r == 0) ? v2.x : (r == 1) ? v2.y : (r == 2) ? v2.z : v2.w;
                const float e3 = (r == 0) ? v3.x : (r == 1) ? v3.y : (r == 2) ? v3.z : v3.w;
                a0 = fmaf(e0, wv, a0);
                a1 = fmaf(e1, wv, a1);
                a2 = fmaf(e2, wv, a2);
                a3 = fmaf(e3, wv, a3);
            }
        }
        out_sc[(size_t)(tbase + r0 + 0) * SSC + lane] = a0;
        out_sc[(size_t)(tbase + r0 + 1) * SSC + lane] = a1;
        out_sc[(size_t)(tbase + r0 + 2) * SSC + lane] = a2;
        out_sc[(size_t)(tbase + r0 + 3) * SSC + lane] = a3;
    }
}

// ---------------------------------------------------------------------------
extern "C" void kernel_launch(void* const* d_in, const int* in_sizes, int n_in,
                              void* d_out, int out_size)
{
    const float* mv_src   = (const float*)d_in[0];
    const float* mv_skip  = (const float*)d_in[1];
    const float* sc_src   = (const float*)d_in[2];
    const float* sc_skip  = (const float*)d_in[3];
    const float* pos_src  = (const float*)d_in[4];
    const float* pos_tgt  = (const float*)d_in[5];
    const int*   isrc     = (const int*)d_in[6];
    const float* W1_mv    = (const float*)d_in[8];
    const float* W2_mv    = (const float*)d_in[9];
    const float* W1_s     = (const float*)d_in[10];
    const float* b1_s     = (const float*)d_in[11];
    const float* W2_s     = (const float*)d_in[12];
    const float* b2_s     = (const float*)d_in[13];

    float* out_mv = (float*)d_out;
    float* out_sc = out_mv + (size_t)N_TGT * CCH * MVD;

    prep_weff<<<1, 288>>>(W1_mv, W2_mv);
    prep_mv<<<N_SRC, 256>>>(mv_src);
    prep_sc<<<N_SRC / 4, 256>>>(sc_src, W1_s);
    fused_kernel<<<N_TGT / TGT_PER_BLOCK, TPB>>>(
        mv_skip, sc_skip, pos_src, pos_tgt, isrc,
        W1_s, b1_s, W2_s, b2_s, out_mv, out_sc);
}

// round 6
// speedup vs baseline: 1.1527x; 1.1527x over previous
#include <cuda_runtime.h>
#include <cstddef>

#define N_SRC   16384
#define N_TGT   65536
#define KNBR    8
#define CCH     16
#define CSKIP   2
#define SSC     32
#define HID     64
#define MVD     16
#define ROW_MV  (CCH*MVD)      // 256
#define TPB     128
#define TGT_PER_BLOCK 16
#define HA_STRIDE 68
#define SK_STRIDE 36
#define PREP_ROWS 16

__device__ float g_mvT[(size_t)N_SRC * ROW_MV]; // mv_src @ Weff[0:16]  (16 MB)
__device__ float g_scT[(size_t)N_SRC * HID];    // sc_src @ W1a         (4 MB)

__device__ __forceinline__ float gelu_tanh(float x)
{
    const float c0 = 0.7978845608028654f;
    float u = c0 * fmaf(0.044715f * x, x * x, x);
    float t = tanhf(u);
    return 0.5f * x * (1.0f + t);
}

// ---------------------------------------------------------------------------
// Combined prep: per block of 16 source rows, compute
//   g_mvT[s] = mv_src[s] @ Weff[0:16]   (Weff computed per-block)
//   g_scT[s] = sc_src[s] @ W1a
// ---------------------------------------------------------------------------
__global__ __launch_bounds__(256) void prep_all(
    const float* __restrict__ mv_src, const float* __restrict__ sc_src,
    const float* __restrict__ W1_mv,  const float* __restrict__ W2_mv,
    const float* __restrict__ W1_s)
{
    __shared__ __align__(16) float we[CCH * CCH];          // 1 KB (rows 0..15 only)
    __shared__ __align__(16) float rows[PREP_ROWS * 256];  // 16 KB
    __shared__ __align__(16) float w1a[SSC * HID];         // 8 KB
    __shared__ __align__(16) float xs[PREP_ROWS][SSC + 1]; // 2.1 KB

    const int tid = threadIdx.x;
    const int s0  = blockIdx.x * PREP_ROWS;

    // Weff[cp][c] for cp<16 (each thread one entry)
    {
        const int cp = tid >> 4, c = tid & 15;
        float acc = 0.f;
        #pragma unroll
        for (int h = 0; h < HID; h++)
            acc = fmaf(__ldg(W1_mv + cp * HID + h), __ldg(W2_mv + h * CCH + c), acc);
        we[tid] = acc;
    }
    // stage 16 mv rows (4096 floats) as float4
    {
        const float4* src = (const float4*)(mv_src + (size_t)s0 * 256);
        float4* dst = (float4*)rows;
        #pragma unroll
        for (int i = 0; i < 4; i++) dst[tid + 256 * i] = __ldg(src + tid + 256 * i);
    }
    // stage W1a (2048 floats)
    #pragma unroll
    for (int i = 0; i < 8; i++) w1a[tid + 256 * i] = __ldg(W1_s + tid + 256 * i);
    // stage sc rows (512 floats)
    {
        const int r = tid >> 5, j = tid & 31;
        xs[r][j]     = __ldg(sc_src + (size_t)(s0 + r) * SSC + j);
        xs[r + 8][j] = __ldg(sc_src + (size_t)(s0 + r + 8) * SSC + j);
    }
    __syncthreads();

    // mvT: thread (c,i) = tid, loop rows
    {
        const int c = tid >> 4, i = tid & 15;
        #pragma unroll 4
        for (int r = 0; r < PREP_ROWS; r++) {
            const float* row = rows + r * 256;
            float acc = 0.f;
            #pragma unroll
            for (int cp = 0; cp < 16; cp++)
                acc = fmaf(row[cp * 16 + i], we[cp * 16 + c], acc);
            g_mvT[(size_t)(s0 + r) * 256 + tid] = acc;
        }
    }
    // scT: thread handles (r, h) for 4 r values
    {
        const int h = tid & 63;
        #pragma unroll
        for (int rr = 0; rr < 4; rr++) {
            const int r = (tid >> 6) * 4 + rr;
            float acc = 0.f;
            #pragma unroll
            for (int j = 0; j < 32; j++)
                acc = fmaf(xs[r][j], w1a[j * HID + h], acc);
            g_scT[(size_t)(s0 + r) * HID + h] = acc;
        }
    }
}

// ---------------------------------------------------------------------------
// Warp-private pipeline: warp w owns targets {4w .. 4w+3}.
// Gather reads PRE-TRANSFORMED sources, so the accumulator IS the output.
// ---------------------------------------------------------------------------
__global__ __launch_bounds__(TPB, 6) void fused_kernel(
    const float* __restrict__ mv_skip, const float* __restrict__ sc_skip,
    const float* __restrict__ pos_src, const float* __restrict__ pos_tgt,
    const int*   __restrict__ isrc,
    const float* __restrict__ W1_mv,   const float* __restrict__ W2_mv,
    const float* __restrict__ W1_s,    const float* __restrict__ b1_s,
    const float* __restrict__ W2_s,    const float* __restrict__ b2_s,
    float* __restrict__ out_mv,        float* __restrict__ out_sc)
{
    __shared__ __align__(16) float sHA[TGT_PER_BLOCK * HA_STRIDE];  // interp hidden, then h in-place
    __shared__ __align__(16) float sSK[TGT_PER_BLOCK * SK_STRIDE];  // sc_skip stage
    __shared__ __align__(16) float sWsk[2 * CCH];                   // Weff rows 16,17

    const int tid  = threadIdx.x;
    const int lane = tid & 31;
    const int warp = tid >> 5;               // 0..3, owns rows 4w..4w+3
    const int tbase = blockIdx.x * TGT_PER_BLOCK;
    const int r0 = warp * 4;

    // Weff rows 16..17 (skip channels), computed by warp 0
    if (tid < 32) {
        const int cp = 16 + (tid >> 4), c = tid & 15;
        float acc = 0.f;
        #pragma unroll
        for (int h = 0; h < HID; h++)
            acc = fmaf(__ldg(W1_mv + cp * HID + h), __ldg(W2_mv + h * CCH + c), acc);
        sWsk[tid] = acc;
    }
    __syncthreads();

    // ---------------- Phase 1: IDW gather of transformed sources ------------
    #pragma unroll
    for (int u = 0; u < 4; u++) {
        const int tl = r0 + u;
        const int t  = tbase + tl;

        float wk = 0.f;
        int   sk = 0;
        if (lane < KNBR) {
            sk = isrc[t * KNBR + lane];
            float dx = pos_src[sk * 3 + 0] - pos_tgt[t * 3 + 0];
            float dy = pos_src[sk * 3 + 1] - pos_tgt[t * 3 + 1];
            float dz = pos_src[sk * 3 + 2] - pos_tgt[t * 3 + 2];
            float d2 = fmaf(dx, dx, fmaf(dy, dy, dz * dz));
            d2 = fmaxf(d2, 1e-16f);
            wk = 1.0f / d2;
        }
        float den = wk;
        #pragma unroll
        for (int o = 16; o; o >>= 1) den += __shfl_xor_sync(0xffffffffu, den, o);
        const float invd = 1.0f / den;

        float4 a0 = make_float4(0.f, 0.f, 0.f, 0.f);
        float4 a1 = make_float4(0.f, 0.f, 0.f, 0.f);
        float  h0 = 0.f, h1 = 0.f;
        #pragma unroll
        for (int k = 0; k < KNBR; k++) {
            const float w = __shfl_sync(0xffffffffu, wk, k);
            const int   s = __shfl_sync(0xffffffffu, sk, k);
            const float4* row = (const float4*)(g_mvT + (size_t)s * ROW_MV);
            float4 v0 = __ldg(row + lane);
            float4 v1 = __ldg(row + lane + 32);
            a0.x = fmaf(w, v0.x, a0.x); a0.y = fmaf(w, v0.y, a0.y);
            a0.z = fmaf(w, v0.z, a0.z); a0.w = fmaf(w, v0.w, a0.w);
            a1.x = fmaf(w, v1.x, a1.x); a1.y = fmaf(w, v1.y, a1.y);
            a1.z = fmaf(w, v1.z, a1.z); a1.w = fmaf(w, v1.w, a1.w);
            h0 = fmaf(w, __ldg(g_scT + (size_t)s * HID + lane), h0);
            h1 = fmaf(w, __ldg(g_scT + (size_t)s * HID + 32 + lane), h1);
        }
        a0.x *= invd; a0.y *= invd; a0.z *= invd; a0.w *= invd;
        a1.x *= invd; a1.y *= invd; a1.z *= invd; a1.w *= invd;

        // skip correction: out[c][i] += skip0[i]*We[16][c] + skip1[i]*We[17][c]
        const int c0 = lane >> 2;
        const int ib = 4 * (lane & 3);
        float4 sk0 = __ldg((const float4*)(mv_skip + (size_t)t * 32 + ib));
        float4 sk1 = __ldg((const float4*)(mv_skip + (size_t)t * 32 + 16 + ib));
        const float wa16 = sWsk[c0];
        const float wa17 = sWsk[16 + c0];
        const float wb16 = sWsk[c0 + 8];
        const float wb17 = sWsk[16 + c0 + 8];
        a0.x = fmaf(sk0.x, wa16, fmaf(sk1.x, wa17, a0.x));
        a0.y = fmaf(sk0.y, wa16, fmaf(sk1.y, wa17, a0.y));
        a0.z = fmaf(sk0.z, wa16, fmaf(sk1.z, wa17, a0.z));
        a0.w = fmaf(sk0.w, wa16, fmaf(sk1.w, wa17, a0.w));
        a1.x = fmaf(sk0.x, wb16, fmaf(sk1.x, wb17, a1.x));
        a1.y = fmaf(sk0.y, wb16, fmaf(sk1.y, wb17, a1.y));
        a1.z = fmaf(sk0.z, wb16, fmaf(sk1.z, wb17, a1.z));
        a1.w = fmaf(sk0.w, wb16, fmaf(sk1.w, wb17, a1.w));

        float4* dst = (float4*)(out_mv + (size_t)t * ROW_MV);
        dst[lane]      = a0;
        dst[lane + 32] = a1;

        sHA[tl * HA_STRIDE + lane]      = h0 * invd;
        sHA[tl * HA_STRIDE + 32 + lane] = h1 * invd;
        sSK[tl * SK_STRIDE + lane]      = sc_skip[(size_t)t * SSC + lane];
    }
    __syncwarp();

    // ---------------- Phase 3a: hidden = gelu(interp_part + skip@W1b + b1) --
    {
        float2 bb = __ldg((const float2*)(b1_s + 2 * lane));
        float2 i0 = *(const float2*)(sHA + (r0 + 0) * HA_STRIDE + 2 * lane);
        float2 i1 = *(const float2*)(sHA + (r0 + 1) * HA_STRIDE + 2 * lane);
        float2 i2 = *(const float2*)(sHA + (r0 + 2) * HA_STRIDE + 2 * lane);
        float2 i3 = *(const float2*)(sHA + (r0 + 3) * HA_STRIDE + 2 * lane);
        float a0x = bb.x + i0.x, a0y = bb.y + i0.y;
        float a1x = bb.x + i1.x, a1y = bb.y + i1.y;
        float a2x = bb.x + i2.x, a2y = bb.y + i2.y;
        float a3x = bb.x + i3.x, a3y = bb.y + i3.y;
        const float* x0 = sSK + (r0 + 0) * SK_STRIDE;
        const float* x1 = sSK + (r0 + 1) * SK_STRIDE;
        const float* x2 = sSK + (r0 + 2) * SK_STRIDE;
        const float* x3 = sSK + (r0 + 3) * SK_STRIDE;
        #pragma unroll
        for (int jc = 0; jc < 8; jc++) {
            float4 v0 = *(const float4*)(x0 + 4 * jc);
            float4 v1 = *(const float4*)(x1 + 4 * jc);
            float4 v2 = *(const float4*)(x2 + 4 * jc);
            float4 v3 = *(const float4*)(x3 + 4 * jc);
            #pragma unroll
            for (int r = 0; r < 4; r++) {
                const int j = 4 * jc + r;
                float2 wv = __ldg((const float2*)(W1_s + (SSC + j) * HID + 2 * lane));
                const float e0 = (r == 0) ? v0.x : (r == 1) ? v0.y : (r == 2) ? v0.z : v0.w;
                const float e1 = (r == 0) ? v1.x : (r == 1) ? v1.y : (r == 2) ? v1.z : v1.w;
                const float e2 = (r == 0) ? v2.x : (r == 1) ? v2.y : (r == 2) ? v2.z : v2.w;
                const float e3 = (r == 0) ? v3.x : (r == 1) ? v3.y : (r == 2) ? v3.z : v3.w;
                a0x = fmaf(e0, wv.x, a0x); a0y = fmaf(e0, wv.y, a0y);
                a1x = fmaf(e1, wv.x, a1x); a1y = fmaf(e1, wv.y, a1y);
                a2x = fmaf(e2, wv.x, a2x); a2y = fmaf(e2, wv.y, a2y);
                a3x = fmaf(e3, wv.x, a3x); a3y = fmaf(e3, wv.y, a3y);
            }
        }
        *(float2*)(sHA + (r0 + 0) * HA_STRIDE + 2 * lane) = make_float2(gelu_tanh(a0x), gelu_tanh(a0y));
        *(float2*)(sHA + (r0 + 1) * HA_STRIDE + 2 * lane) = make_float2(gelu_tanh(a1x), gelu_tanh(a1y));
        *(float2*)(sHA + (r0 + 2) * HA_STRIDE + 2 * lane) = make_float2(gelu_tanh(a2x), gelu_tanh(a2y));
        *(float2*)(sHA + (r0 + 3) * HA_STRIDE + 2 * lane) = make_float2(gelu_tanh(a3x), gelu_tanh(a3y));
    }
    __syncwarp();

    // ---------------- Phase 3b: scalar output (lane = channel) --------------
    {
        const float bb = __ldg(b2_s + lane);
        float a0 = bb, a1 = bb, a2 = bb, a3 = bb;
        const float* h0 = sHA + (r0 + 0) * HA_STRIDE;
        const float* h1 = sHA + (r0 + 1) * HA_STRIDE;
        const float* h2 = sHA + (r0 + 2) * HA_STRIDE;
        const float* h3 = sHA + (r0 + 3) * HA_STRIDE;
        #pragma unroll
        for (int hc = 0; hc < 16; hc++) {
            float4 v0 = *(const float4*)(h0 + 4 * hc);
            float4 v1 = *(const float4*)(h1 + 4 * hc);
            float4 v2 = *(const float4*)(h2 + 4 * hc);
            float4 v3 = *(const float4*)(h3 + 4 * hc);
            #pragma unroll
            for (int r = 0; r < 4; r++) {
                const int j = 4 * hc + r;
                float wv = __ldg(W2_s + j * SSC + lane);
                const float e0 = (r == 0) ? v0.x : (r == 1) ? v0.y : (r == 2) ? v0.z : v0.w;
                const float e1 = (r == 0) ? v1.x : (r == 1) ? v1.y : (r == 2) ? v1.z : v1.w;
                const float e2 = (r == 0) ? v2.x : (r == 1) ? v2.y : (r == 2) ? v2.z : v2.w;
                const float e3 = (r == 0) ? v3.x : (r == 1) ? v3.y : (r == 2) ? v3.z : v3.w;
                a0 = fmaf(e0, wv, a0);
                a1 = fmaf(e1, wv, a1);
                a2 = fmaf(e2, wv, a2);
                a3 = fmaf(e3, wv, a3);
            }
        }
        out_sc[(size_t)(tbase + r0 + 0) * SSC + lane] = a0;
        out_sc[(size_t)(tbase + r0 + 1) * SSC + lane] = a1;
        out_sc[(size_t)(tbase + r0 + 2) * SSC + lane] = a2;
        out_sc[(size_t)(tbase + r0 + 3) * SSC + lane] = a3;
    }
}

// ---------------------------------------------------------------------------
extern "C" void kernel_launch(void* const* d_in, const int* in_sizes, int n_in,
                              void* d_out, int out_size)
{
    const float* mv_src   = (const float*)d_in[0];
    const float* mv_skip  = (const float*)d_in[1];
    const float* sc_src   = (const float*)d_in[2];
    const float* sc_skip  = (const float*)d_in[3];
    const float* pos_src  = (const float*)d_in[4];
    const float* pos_tgt  = (const float*)d_in[5];
    const int*   isrc     = (const int*)d_in[6];
    const float* W1_mv    = (const float*)d_in[8];
    const float* W2_mv    = (const float*)d_in[9];
    const float* W1_s     = (const float*)d_in[10];
    const float* b1_s     = (const float*)d_in[11];
    const float* W2_s     = (const float*)d_in[12];
    const float* b2_s     = (const float*)d_in[13];

    float* out_mv = (float*)d_out;
    float* out_sc = out_mv + (size_t)N_TGT * CCH * MVD;

    prep_all<<<N_SRC / PREP_ROWS, 256>>>(mv_src, sc_src, W1_mv, W2_mv, W1_s);
    fused_kernel<<<N_TGT / TGT_PER_BLOCK, TPB>>>(
        mv_skip, sc_skip, pos_src, pos_tgt, isrc,
        W1_mv, W2_mv, W1_s, b1_s, W2_s, b2_s, out_mv, out_sc);
}

// round 7
// speedup vs baseline: 1.2010x; 1.0419x over previous
#include <cuda_runtime.h>
#include <cuda_fp16.h>
#include <cstddef>

#define N_SRC   16384
#define N_TGT   65536
#define KNBR    8
#define CCH     16
#define CSKIP   2
#define SSC     32
#define HID     64
#define MVD     16
#define ROW_MV  (CCH*MVD)      // 256
#define TPB     128
#define TGT_PER_BLOCK 16
#define HA_STRIDE 68
#define SK_STRIDE 36
#define PREP_ROWS 16

__device__ __half g_mvTh[(size_t)N_SRC * ROW_MV]; // mv_src @ Weff[0:16]  (8 MB, fp16)
__device__ __half g_scTh[(size_t)N_SRC * HID];    // sc_src @ W1a         (2 MB, fp16)
__device__ __half g_w1bh[SSC * HID];              // W1_s rows 32..63     (4 KB, fp16)

__device__ __forceinline__ float gelu_tanh(float x)
{
    const float c0 = 0.7978845608028654f;
    float u = c0 * fmaf(0.044715f * x, x * x, x);
    float t = tanhf(u);
    return 0.5f * x * (1.0f + t);
}

// ---------------------------------------------------------------------------
// Combined prep (fp16 outputs): per block of 16 source rows
// ---------------------------------------------------------------------------
__global__ __launch_bounds__(256) void prep_all(
    const float* __restrict__ mv_src, const float* __restrict__ sc_src,
    const float* __restrict__ W1_mv,  const float* __restrict__ W2_mv,
    const float* __restrict__ W1_s)
{
    __shared__ __align__(16) float we[CCH * CCH];          // 1 KB
    __shared__ __align__(16) float rows[PREP_ROWS * 256];  // 16 KB
    __shared__ __align__(16) float w1a[SSC * HID];         // 8 KB
    __shared__ __align__(16) float xs[PREP_ROWS][SSC + 1]; // 2.1 KB

    const int tid = threadIdx.x;
    const int s0  = blockIdx.x * PREP_ROWS;

    // Weff[cp][c] for cp<16
    {
        const int cp = tid >> 4, c = tid & 15;
        float acc = 0.f;
        #pragma unroll
        for (int h = 0; h < HID; h++)
            acc = fmaf(__ldg(W1_mv + cp * HID + h), __ldg(W2_mv + h * CCH + c), acc);
        we[tid] = acc;
    }
    // stage 16 mv rows (4096 floats)
    {
        const float4* src = (const float4*)(mv_src + (size_t)s0 * 256);
        float4* dst = (float4*)rows;
        #pragma unroll
        for (int i = 0; i < 4; i++) dst[tid + 256 * i] = __ldg(src + tid + 256 * i);
    }
    // stage W1a (2048 floats)
    #pragma unroll
    for (int i = 0; i < 8; i++) w1a[tid + 256 * i] = __ldg(W1_s + tid + 256 * i);
    // stage sc rows (512 floats)
    {
        const int r = tid >> 5, j = tid & 31;
        xs[r][j]     = __ldg(sc_src + (size_t)(s0 + r) * SSC + j);
        xs[r + 8][j] = __ldg(sc_src + (size_t)(s0 + r + 8) * SSC + j);
    }
    // W1b fp16 copy (block 0 only)
    if (blockIdx.x == 0) {
        #pragma unroll
        for (int i = 0; i < 8; i++) {
            const int idx = tid + 256 * i;               // 0..2047
            g_w1bh[idx] = __float2half_rn(__ldg(W1_s + SSC * HID + idx));
        }
    }
    __syncthreads();

    // mvT fp16: 8 passes x 2 rows; thread -> (row half, pair p)
    {
        const int rh = tid >> 7;            // 0..1
        const int p  = tid & 127;
        const int c  = p >> 3;
        const int i0 = (p & 7) * 2;
        #pragma unroll 2
        for (int it = 0; it < 8; it++) {
            const int r = 2 * it + rh;
            const float* row = rows + r * 256;
            float a0 = 0.f, a1 = 0.f;
            #pragma unroll
            for (int cp = 0; cp < 16; cp++) {
                const float wv = we[cp * 16 + c];
                a0 = fmaf(row[cp * 16 + i0],     wv, a0);
                a1 = fmaf(row[cp * 16 + i0 + 1], wv, a1);
            }
            *(__half2*)(g_mvTh + (size_t)(s0 + r) * 256 + c * 16 + i0) =
                __floats2half2_rn(a0, a1);
        }
    }
    // scT fp16: 2 passes x 8 rows; thread -> (row, h pair)
    {
        const int h0 = (tid & 31) * 2;
        #pragma unroll
        for (int it = 0; it < 2; it++) {
            const int r = it * 8 + (tid >> 5);
            float a0 = 0.f, a1 = 0.f;
            #pragma unroll
            for (int j = 0; j < 32; j++) {
                const float x = xs[r][j];
                a0 = fmaf(x, w1a[j * HID + h0],     a0);
                a1 = fmaf(x, w1a[j * HID + h0 + 1], a1);
            }
            *(__half2*)(g_scTh + (size_t)(s0 + r) * HID + h0) =
                __floats2half2_rn(a0, a1);
        }
    }
}

// ---------------------------------------------------------------------------
// Warp-private pipeline: warp w owns targets {4w .. 4w+3}.
// ---------------------------------------------------------------------------
__global__ __launch_bounds__(TPB, 6) void fused_kernel(
    const float* __restrict__ mv_skip, const float* __restrict__ sc_skip,
    const float* __restrict__ pos_src, const float* __restrict__ pos_tgt,
    const int*   __restrict__ isrc,
    const float* __restrict__ W1_mv,   const float* __restrict__ W2_mv,
    const float* __restrict__ b1_s,
    const float* __restrict__ W2_s,    const float* __restrict__ b2_s,
    float* __restrict__ out_mv,        float* __restrict__ out_sc)
{
    __shared__ __align__(16) float sHA[TGT_PER_BLOCK * HA_STRIDE];
    __shared__ __align__(16) float sSK[TGT_PER_BLOCK * SK_STRIDE];
    __shared__ __align__(16) float sWsk[2 * CCH];

    const int tid  = threadIdx.x;
    const int lane = tid & 31;
    const int warp = tid >> 5;
    const int tbase = blockIdx.x * TGT_PER_BLOCK;
    const int r0 = warp * 4;

    // Weff rows 16..17 (skip channels), warp 0
    if (tid < 32) {
        const int cp = 16 + (tid >> 4), c = tid & 15;
        float acc = 0.f;
        #pragma unroll
        for (int h = 0; h < HID; h++)
            acc = fmaf(__ldg(W1_mv + cp * HID + h), __ldg(W2_mv + h * CCH + c), acc);
        sWsk[tid] = acc;
    }
    __syncthreads();

    // ---------------- Phase 1: IDW gather of fp16 transformed sources -------
    #pragma unroll
    for (int u = 0; u < 4; u++) {
        const int tl = r0 + u;
        const int t  = tbase + tl;

        float wk = 0.f;
        int   sk = 0;
        if (lane < KNBR) {
            sk = isrc[t * KNBR + lane];
            float dx = pos_src[sk * 3 + 0] - pos_tgt[t * 3 + 0];
            float dy = pos_src[sk * 3 + 1] - pos_tgt[t * 3 + 1];
            float dz = pos_src[sk * 3 + 2] - pos_tgt[t * 3 + 2];
            float d2 = fmaf(dx, dx, fmaf(dy, dy, dz * dz));
            d2 = fmaxf(d2, 1e-16f);
            wk = 1.0f / d2;
        }
        float den = wk;
        #pragma unroll
        for (int o = 16; o; o >>= 1) den += __shfl_xor_sync(0xffffffffu, den, o);
        const float invd = 1.0f / den;

        float acc[8];
        #pragma unroll
        for (int j = 0; j < 8; j++) acc[j] = 0.f;
        float h0 = 0.f, h1 = 0.f;

        #pragma unroll
        for (int k = 0; k < KNBR; k++) {
            const float w = __shfl_sync(0xffffffffu, wk, k);
            const int   s = __shfl_sync(0xffffffffu, sk, k);
            // lane covers elements 8*lane .. 8*lane+7 of the 256-half row
            uint4 v = __ldg((const uint4*)(g_mvTh + (size_t)s * ROW_MV) + lane);
            const __half2* hv = (const __half2*)&v;
            float2 f0 = __half22float2(hv[0]);
            float2 f1 = __half22float2(hv[1]);
            float2 f2 = __half22float2(hv[2]);
            float2 f3 = __half22float2(hv[3]);
            acc[0] = fmaf(w, f0.x, acc[0]); acc[1] = fmaf(w, f0.y, acc[1]);
            acc[2] = fmaf(w, f1.x, acc[2]); acc[3] = fmaf(w, f1.y, acc[3]);
            acc[4] = fmaf(w, f2.x, acc[4]); acc[5] = fmaf(w, f2.y, acc[5]);
            acc[6] = fmaf(w, f3.x, acc[6]); acc[7] = fmaf(w, f3.y, acc[7]);
            __half2 sv = __ldg((const __half2*)(g_scTh + (size_t)s * HID) + lane);
            float2 sf = __half22float2(sv);
            h0 = fmaf(w, sf.x, h0); h1 = fmaf(w, sf.y, h1);
        }

        // skip correction for channel c = lane>>1, blades ib..ib+7
        const int c  = lane >> 1;
        const int ib = (lane & 1) * 8;
        float4 s0a = __ldg((const float4*)(mv_skip + (size_t)t * 32 + ib));
        float4 s0b = __ldg((const float4*)(mv_skip + (size_t)t * 32 + ib + 4));
        float4 s1a = __ldg((const float4*)(mv_skip + (size_t)t * 32 + 16 + ib));
        float4 s1b = __ldg((const float4*)(mv_skip + (size_t)t * 32 + 16 + ib + 4));
        const float w16 = sWsk[c];
        const float w17 = sWsk[16 + c];

        float4 o0, o1;
        o0.x = fmaf(acc[0], invd, fmaf(s0a.x, w16, s1a.x * w17));
        o0.y = fmaf(acc[1], invd, fmaf(s0a.y, w16, s1a.y * w17));
        o0.z = fmaf(acc[2], invd, fmaf(s0a.z, w16, s1a.z * w17));
        o0.w = fmaf(acc[3], invd, fmaf(s0a.w, w16, s1a.w * w17));
        o1.x = fmaf(acc[4], invd, fmaf(s0b.x, w16, s1b.x * w17));
        o1.y = fmaf(acc[5], invd, fmaf(s0b.y, w16, s1b.y * w17));
        o1.z = fmaf(acc[6], invd, fmaf(s0b.z, w16, s1b.z * w17));
        o1.w = fmaf(acc[7], invd, fmaf(s0b.w, w16, s1b.w * w17));

        float4* dst = (float4*)(out_mv + (size_t)t * ROW_MV + 8 * lane);
        dst[0] = o0;
        dst[1] = o1;

        *(float2*)(sHA + tl * HA_STRIDE + 2 * lane) = make_float2(h0 * invd, h1 * invd);
        sSK[tl * SK_STRIDE + lane] = sc_skip[(size_t)t * SSC + lane];
    }
    __syncwarp();

    // ---------------- Phase 3a: hidden = gelu(interp_part + skip@W1b + b1) --
    {
        float2 bb = __ldg((const float2*)(b1_s + 2 * lane));
        float2 i0 = *(const float2*)(sHA + (r0 + 0) * HA_STRIDE + 2 * lane);
        float2 i1 = *(const float2*)(sHA + (r0 + 1) * HA_STRIDE + 2 * lane);
        float2 i2 = *(const float2*)(sHA + (r0 + 2) * HA_STRIDE + 2 * lane);
        float2 i3 = *(const float2*)(sHA + (r0 + 3) * HA_STRIDE + 2 * lane);
        float a0x = bb.x + i0.x, a0y = bb.y + i0.y;
        float a1x = bb.x + i1.x, a1y = bb.y + i1.y;
        float a2x = bb.x + i2.x, a2y = bb.y + i2.y;
        float a3x = bb.x + i3.x, a3y = bb.y + i3.y;
        const float* x0 = sSK + (r0 + 0) * SK_STRIDE;
        const float* x1 = sSK + (r0 + 1) * SK_STRIDE;
        const float* x2 = sSK + (r0 + 2) * SK_STRIDE;
        const float* x3 = sSK + (r0 + 3) * SK_STRIDE;
        #pragma unroll
        for (int jc = 0; jc < 8; jc++) {
            float4 v0 = *(const float4*)(x0 + 4 * jc);
            float4 v1 = *(const float4*)(x1 + 4 * jc);
            float4 v2 = *(const float4*)(x2 + 4 * jc);
            float4 v3 = *(const float4*)(x3 + 4 * jc);
            #pragma unroll
            for (int r = 0; r < 4; r++) {
                const int j = 4 * jc + r;
                __half2 wh = __ldg((const __half2*)(g_w1bh + j * HID + 2 * lane));
                float2 wv = __half22float2(wh);
                const float e0 = (r == 0) ? v0.x : (r == 1) ? v0.y : (r == 2) ? v0.z : v0.w;
                const float e1 = (r == 0) ? v1.x : (r == 1) ? v1.y : (r == 2) ? v1.z : v1.w;
                const float e2 = (r == 0) ? v2.x : (r == 1) ? v2.y : (r == 2) ? v2.z : v2.w;
                const float e3 = (r == 0) ? v3.x : (r == 1) ? v3.y : (r == 2) ? v3.z : v3.w;
                a0x = fmaf(e0, wv.x, a0x); a0y = fmaf(e0, wv.y, a0y);
                a1x = fmaf(e1, wv.x, a1x); a1y = fmaf(e1, wv.y, a1y);
                a2x = fmaf(e2, wv.x, a2x); a2y = fmaf(e2, wv.y, a2y);
                a3x = fmaf(e3, wv.x, a3x); a3y = fmaf(e3, wv.y, a3y);
            }
        }
        *(float2*)(sHA + (r0 + 0) * HA_STRIDE + 2 * lane) = make_float2(gelu_tanh(a0x), gelu_tanh(a0y));
        *(float2*)(sHA + (r0 + 1) * HA_STRIDE + 2 * lane) = make_float2(gelu_tanh(a1x), gelu_tanh(a1y));
        *(float2*)(sHA + (r0 + 2) * HA_STRIDE + 2 * lane) = make_float2(gelu_tanh(a2x), gelu_tanh(a2y));
        *(float2*)(sHA + (r0 + 3) * HA_STRIDE + 2 * lane) = make_float2(gelu_tanh(a3x), gelu_tanh(a3y));
    }
    __syncwarp();

    // ---------------- Phase 3b: scalar output (lane = channel) --------------
    {
        const float bb = __ldg(b2_s + lane);
        float a0 = bb, a1 = bb, a2 = bb, a3 = bb;
        const float* h0 = sHA + (r0 + 0) * HA_STRIDE;
        const float* h1 = sHA + (r0 + 1) * HA_STRIDE;
        const float* h2 = sHA + (r0 + 2) * HA_STRIDE;
        const float* h3 = sHA + (r0 + 3) * HA_STRIDE;
        #pragma unroll
        for (int hc = 0; hc < 16; hc++) {
            float4 v0 = *(const float4*)(h0 + 4 * hc);
            float4 v1 = *(const float4*)(h1 + 4 * hc);
            float4 v2 = *(const float4*)(h2 + 4 * hc);
            float4 v3 = *(const float4*)(h3 + 4 * hc);
            #pragma unroll
            for (int r = 0; r < 4; r++) {
                const int j = 4 * hc + r;
                float wv = __ldg(W2_s + j * SSC + lane);
                const float e0 = (r == 0) ? v0.x : (r == 1) ? v0.y : (r == 2) ? v0.z : v0.w;
                const float e1 = (r == 0) ? v1.x : (r == 1) ? v1.y : (r == 2) ? v1.z : v1.w;
                const float e2 = (r == 0) ? v2.x : (r == 1) ? v2.y : (r == 2) ? v2.z : v2.w;
                const float e3 = (r == 0) ? v3.x : (r == 1) ? v3.y : (r == 2) ? v3.z : v3.w;
                a0 = fmaf(e0, wv, a0);
                a1 = fmaf(e1, wv, a1);
                a2 = fmaf(e2, wv, a2);
                a3 = fmaf(e3, wv, a3);
            }
        }
        out_sc[(size_t)(tbase + r0 + 0) * SSC + lane] = a0;
        out_sc[(size_t)(tbase + r0 + 1) * SSC + lane] = a1;
        out_sc[(size_t)(tbase + r0 + 2) * SSC + lane] = a2;
        out_sc[(size_t)(tbase + r0 + 3) * SSC + lane] = a3;
    }
}

// ---------------------------------------------------------------------------
extern "C" void kernel_launch(void* const* d_in, const int* in_sizes, int n_in,
                              void* d_out, int out_size)
{
    const float* mv_src   = (const float*)d_in[0];
    const float* mv_skip  = (const float*)d_in[1];
    const float* sc_src   = (const float*)d_in[2];
    const float* sc_skip  = (const float*)d_in[3];
    const float* pos_src  = (const float*)d_in[4];
    const float* pos_tgt  = (const float*)d_in[5];
    const int*   isrc     = (const int*)d_in[6];
    const float* W1_mv    = (const float*)d_in[8];
    const float* W2_mv    = (const float*)d_in[9];
    const float* W1_s     = (const float*)d_in[10];
    const float* b1_s     = (const float*)d_in[11];
    const float* W2_s     = (const float*)d_in[12];
    const float* b2_s     = (const float*)d_in[13];

    float* out_mv = (float*)d_out;
    float* out_sc = out_mv + (size_t)N_TGT * CCH * MVD;

    prep_all<<<N_SRC / PREP_ROWS, 256>>>(mv_src, sc_src, W1_mv, W2_mv, W1_s);
    fused_kernel<<<N_TGT / TGT_PER_BLOCK, TPB>>>(
        mv_skip, sc_skip, pos_src, pos_tgt, isrc,
        W1_mv, W2_mv, b1_s, W2_s, b2_s, out_mv, out_sc);
}